// round 7
// baseline (speedup 1.0000x reference)
#include <cuda_runtime.h>
#include <cuda_bf16.h>
#include <cstdint>

#define NN 512
#define NE (NN * NN)

// ---------------- device scratch (no allocation allowed) ----------------
__device__ int g_cnt[NN];
__device__ int g_off[NN];
__device__ int g_nodeStart[NN + 1];
__device__ int g_perm[NE];
__device__ __align__(16) float g_h1[NN * 36];
__device__ __align__(16) float g_h2[NN * 24];
__device__ __align__(16) float g_h3[NN * 5];

// ---------------- counting sort by dst ----------------
__global__ void k_zero() {
    int t = threadIdx.x;
    if (t < NN) g_cnt[t] = 0;
}

__global__ void k_hist(const int* __restrict__ dst) {
    int t = blockIdx.x * blockDim.x + threadIdx.x;
    int stride = gridDim.x * blockDim.x;
    for (int e = t; e < NE; e += stride) atomicAdd(&g_cnt[dst[e]], 1);
}

__global__ void k_scan() {
    __shared__ int sc[NN];
    int n = threadIdx.x;               // 512 threads
    int v = g_cnt[n];
    sc[n] = v;
    __syncthreads();
    for (int off = 1; off < NN; off <<= 1) {
        int t = (n >= off) ? sc[n - off] : 0;
        __syncthreads();
        sc[n] += t;
        __syncthreads();
    }
    int incl = sc[n];
    int excl = incl - v;
    g_nodeStart[n] = excl;
    g_off[n] = excl;
    if (n == NN - 1) g_nodeStart[NN] = incl;
}

__global__ void k_scatter(const int* __restrict__ dst) {
    int t = blockIdx.x * blockDim.x + threadIdx.x;
    int stride = gridDim.x * blockDim.x;
    for (int e = t; e < NE; e += stride) {
        int p = atomicAdd(&g_off[dst[e]], 1);
        g_perm[p] = e;
    }
}

// ---------------- fused NNConv layer ----------------
// One block per dst node. Edges of the node (contiguous in g_perm) are
// processed 256 slots per iteration (128 threads x TE=2). Per (i,o) the 7
// weight values are loaded once from shared and reused across TE edges.
// Epilogue: warp shfl reduce + cross-warp reduce + mean + root + bias + relu.
template <int CIN, int COUT, int LAYER>
__global__ void __launch_bounds__(128) k_conv(
    const float* __restrict__ xin,   // only used for LAYER==1
    const float* __restrict__ ea,    // [NE, 6]
    const int* __restrict__ src,     // [NE]
    const float* __restrict__ We,    // [6, CIN*COUT]
    const float* __restrict__ be,    // [CIN*COUT]
    const float* __restrict__ root,  // [CIN, COUT]
    const float* __restrict__ bias)  // [COUT]
{
    constexpr int CC = CIN * COUT;
    constexpr int TE = 2;
    const float* hprev = (LAYER == 1) ? xin : (LAYER == 2 ? g_h1 : g_h2);
    float* hout = (LAYER == 1) ? g_h1 : (LAYER == 2 ? g_h2 : g_h3);

    extern __shared__ float sm[];
    float* sH = sm;                 // NN*CIN
    float* sWe = sm + NN * CIN;     // 6*CC
    float* sBe = sWe + 6 * CC;      // CC
    __shared__ float wsum[4 * COUT];

    // cooperative smem fills (all sizes divisible by 4 floats)
    {
        const float4* s1 = (const float4*)hprev;
        float4* d1 = (float4*)sH;
        for (int i = threadIdx.x; i < NN * CIN / 4; i += 128) d1[i] = s1[i];
        const float4* s2 = (const float4*)We;
        float4* d2 = (float4*)sWe;
        for (int i = threadIdx.x; i < 6 * CC / 4; i += 128) d2[i] = s2[i];
        const float4* s3 = (const float4*)be;
        float4* d3 = (float4*)sBe;
        for (int i = threadIdx.x; i < CC / 4; i += 128) d3[i] = s3[i];
    }
    __syncthreads();

    int n = blockIdx.x;
    int start = g_nodeStart[n];
    int end = g_nodeStart[n + 1];

    float acc[COUT];
#pragma unroll
    for (int o = 0; o < COUT; o++) acc[o] = 0.f;

    for (int j0 = start; j0 < end; j0 += 128 * TE) {
        float eaR[TE][6];
        int srcR[TE];
        bool val[TE];
#pragma unroll
        for (int u = 0; u < TE; u++) {
            int j = j0 + u * 128 + threadIdx.x;
            bool v = (j < end);
            int e = g_perm[v ? j : start];
            val[u] = v;
            srcR[u] = src[e];
            const float2* p = (const float2*)(ea + (size_t)e * 6);
            float2 a0 = p[0], a1 = p[1], a2 = p[2];
            eaR[u][0] = a0.x; eaR[u][1] = a0.y; eaR[u][2] = a1.x;
            eaR[u][3] = a1.y; eaR[u][4] = a2.x; eaR[u][5] = a2.y;
        }
#pragma unroll 1
        for (int i = 0; i < CIN; i++) {
            float hs[TE];
#pragma unroll
            for (int u = 0; u < TE; u++)
                hs[u] = val[u] ? sH[srcR[u] * CIN + i] : 0.f;
#pragma unroll
            for (int o = 0; o < COUT; o++) {
                int wi = i * COUT + o;
                float w0 = sWe[wi],          w1 = sWe[CC + wi];
                float w2 = sWe[2 * CC + wi], w3 = sWe[3 * CC + wi];
                float w4 = sWe[4 * CC + wi], w5 = sWe[5 * CC + wi];
                float bb = sBe[wi];
#pragma unroll
                for (int u = 0; u < TE; u++) {
                    float t = fmaf(eaR[u][0], w0, bb);
                    t = fmaf(eaR[u][1], w1, t);
                    t = fmaf(eaR[u][2], w2, t);
                    t = fmaf(eaR[u][3], w3, t);
                    t = fmaf(eaR[u][4], w4, t);
                    t = fmaf(eaR[u][5], w5, t);
                    acc[o] = fmaf(hs[u], fmaxf(t, 0.f), acc[o]);
                }
            }
        }
    }

    // warp butterfly reduce
#pragma unroll
    for (int o = 0; o < COUT; o++) {
        float v = acc[o];
#pragma unroll
        for (int s = 16; s > 0; s >>= 1)
            v += __shfl_xor_sync(0xffffffffu, v, s);
        acc[o] = v;
    }
    int wid = threadIdx.x >> 5, lane = threadIdx.x & 31;
    if (lane == 0) {
#pragma unroll
        for (int o = 0; o < COUT; o++) wsum[wid * COUT + o] = acc[o];
    }
    __syncthreads();
    if (threadIdx.x < COUT) {
        int o = threadIdx.x;
        float s = wsum[o] + wsum[COUT + o] + wsum[2 * COUT + o] + wsum[3 * COUT + o];
        float cnt = (float)(end - start);
        float r = s / fmaxf(cnt, 1.f);
        float d = bias[o];
        for (int i = 0; i < CIN; i++)
            d = fmaf(sH[n * CIN + i], root[i * COUT + o], d);
        hout[n * COUT + o] = fmaxf(r + d, 0.f);
    }
}

// ---------------- pairwise L1 CBT ----------------
__global__ void k_cbt(float* __restrict__ out) {
    __shared__ float sh[NN * 5];
    for (int i = threadIdx.x; i < NN * 5; i += blockDim.x) sh[i] = g_h3[i];
    __syncthreads();
    int gid = blockIdx.x * blockDim.x + threadIdx.x;  // 0 .. NE-1
    int i = gid >> 9;
    int j = gid & (NN - 1);
    float s = 0.f;
#pragma unroll
    for (int k = 0; k < 5; k++)
        s += fabsf(sh[i * 5 + k] - sh[j * 5 + k]);
    out[gid] = s;
}

// ---------------- launcher ----------------
extern "C" void kernel_launch(void* const* d_in, const int* in_sizes, int n_in,
                              void* d_out, int out_size) {
    const float* x     = (const float*)d_in[0];
    const float* ea    = (const float*)d_in[1];
    const int*   ei    = (const int*)d_in[2];
    const float* We1   = (const float*)d_in[3];
    const float* be1   = (const float*)d_in[4];
    const float* root1 = (const float*)d_in[5];
    const float* b1    = (const float*)d_in[6];
    const float* We2   = (const float*)d_in[7];
    const float* be2   = (const float*)d_in[8];
    const float* root2 = (const float*)d_in[9];
    const float* b2    = (const float*)d_in[10];
    const float* We3   = (const float*)d_in[11];
    const float* be3   = (const float*)d_in[12];
    const float* root3 = (const float*)d_in[13];
    const float* b3    = (const float*)d_in[14];
    float* out = (float*)d_out;

    const int* src = ei;
    const int* dst = ei + NE;

    constexpr int SM1 = (NN * 1  + 6 * 36  + 36)  * (int)sizeof(float); //  ~3 KB
    constexpr int SM2 = (NN * 36 + 6 * 864 + 864) * (int)sizeof(float); // ~98 KB
    constexpr int SM3 = (NN * 24 + 6 * 120 + 120) * (int)sizeof(float); // ~53 KB

    cudaFuncSetAttribute((const void*)k_conv<36, 24, 2>,
                         cudaFuncAttributeMaxDynamicSharedMemorySize, SM2);
    cudaFuncSetAttribute((const void*)k_conv<24, 5, 3>,
                         cudaFuncAttributeMaxDynamicSharedMemorySize, SM3);

    k_zero<<<1, NN>>>();
    k_hist<<<256, 256>>>(dst);
    k_scan<<<1, NN>>>();
    k_scatter<<<256, 256>>>(dst);

    k_conv<1, 36, 1><<<NN, 128, SM1>>>(x, ea, src, We1, be1, root1, b1);
    k_conv<36, 24, 2><<<NN, 128, SM2>>>(x, ea, src, We2, be2, root2, b2);
    k_conv<24, 5, 3><<<NN, 128, SM3>>>(x, ea, src, We3, be3, root3, b3);

    k_cbt<<<NE / 256, 256>>>(out);
}

// round 11
// speedup vs baseline: 1.4253x; 1.4253x over previous
#include <cuda_runtime.h>
#include <cuda_bf16.h>
#include <cstdint>

#define NN 512
#define NE (NN * NN)
#define HB 128
#define EPB (NE / HB)

typedef unsigned long long ull;

// ---------------- device scratch (no allocation allowed) ----------------
__device__ int g_hist[HB * NN];
__device__ int g_nodeStart[NN + 1];
__device__ int g_perm[NE];
__device__ __align__(16) float g_h1[NN * 36];
__device__ __align__(16) float g_h2[NN * 24];
__device__ __align__(16) float g_h3[NN * 5];

// ---------------- f32x2 helpers ----------------
__device__ __forceinline__ ull f2fma(ull a, ull b, ull c) {
    ull d;
    asm("fma.rn.f32x2 %0, %1, %2, %3;" : "=l"(d) : "l"(a), "l"(b), "l"(c));
    return d;
}
__device__ __forceinline__ ull f2pk(float lo, float hi) {
    ull r;
    asm("mov.b64 %0, {%1, %2};" : "=l"(r) : "f"(lo), "f"(hi));
    return r;
}
__device__ __forceinline__ void f2un(ull v, float& lo, float& hi) {
    asm("mov.b64 {%0, %1}, %2;" : "=f"(lo), "=f"(hi) : "l"(v));
}

// ---------------- counting sort by dst (privatized histograms) ----------------
__global__ void k_hist(const int* __restrict__ dst) {
    __shared__ int h[NN];
    for (int i = threadIdx.x; i < NN; i += blockDim.x) h[i] = 0;
    __syncthreads();
    int base = blockIdx.x * EPB;
    for (int i = threadIdx.x; i < EPB; i += blockDim.x)
        atomicAdd(&h[dst[base + i]], 1);
    __syncthreads();
    for (int i = threadIdx.x; i < NN; i += blockDim.x)
        g_hist[blockIdx.x * NN + i] = h[i];
}

__global__ void k_scan() {
    __shared__ int sc[NN];
    int n = threadIdx.x;  // 512 threads
    int s = 0;
#pragma unroll 8
    for (int b = 0; b < HB; b++) s += g_hist[b * NN + n];
    sc[n] = s;
    __syncthreads();
    for (int off = 1; off < NN; off <<= 1) {
        int t = (n >= off) ? sc[n - off] : 0;
        __syncthreads();
        sc[n] += t;
        __syncthreads();
    }
    int incl = sc[n];
    int excl = incl - s;
    g_nodeStart[n] = excl;
    if (n == NN - 1) g_nodeStart[NN] = incl;
    int run = excl;
#pragma unroll 8
    for (int b = 0; b < HB; b++) {
        int t = g_hist[b * NN + n];
        g_hist[b * NN + n] = run;
        run += t;
    }
}

__global__ void k_scatter(const int* __restrict__ dst) {
    __shared__ int off[NN];
    for (int i = threadIdx.x; i < NN; i += blockDim.x)
        off[i] = g_hist[blockIdx.x * NN + i];
    __syncthreads();
    int base = blockIdx.x * EPB;
    for (int i = threadIdx.x; i < EPB; i += blockDim.x) {
        int e = base + i;
        int p = atomicAdd(&off[dst[e]], 1);
        g_perm[p] = e;
    }
}

// ---------------- fused NNConv layer, f32x2 over output pairs ----------------
// One block (128 thr) per dst node. 256 edge slots/iter (TE=2). Weights
// repacked in smem per (i, o-pair) as 16 floats:
//   [2v,2v+1]=We[v][i,o0],We[v][i,o1]  v=0..5 ; [12,13]=be pair ; [14,15]=0
// so 4 x LDS.128 yield the 64-bit fma.f32x2 operands directly.
template <int CIN, int COUT, int LAYER>
__global__ void __launch_bounds__(128) k_conv(
    const float* __restrict__ xin,
    const float* __restrict__ ea,
    const int* __restrict__ src,
    const float* __restrict__ We,
    const float* __restrict__ be,
    const float* __restrict__ root,
    const float* __restrict__ bias)
{
    constexpr int CC = CIN * COUT;
    constexpr int OP = (COUT + 1) / 2;
    constexpr int TE = 2;
    const float* hprev = (LAYER == 1) ? xin : (LAYER == 2 ? g_h1 : g_h2);
    float* hout = (LAYER == 1) ? g_h1 : (LAYER == 2 ? g_h2 : g_h3);

    extern __shared__ float sm[];
    float* sH = sm;                    // NN*CIN
    float* sWp = sm + NN * CIN;        // CIN*OP*16
    __shared__ float wsum[4 * 2 * OP];

    // stage h table (sizes divisible by 4 floats)
    {
        const float4* s1 = (const float4*)hprev;
        float4* d1 = (float4*)sH;
        for (int i = threadIdx.x; i < NN * CIN / 4; i += 128) d1[i] = s1[i];
    }
    // repack weights + bias
    for (int idx = threadIdx.x; idx < CIN * OP; idx += 128) {
        int i = idx / OP, op = idx % OP;
        int o0 = 2 * op, o1 = o0 + 1;
        float* w = sWp + idx * 16;
#pragma unroll
        for (int v = 0; v < 6; v++) {
            w[2 * v] = We[v * CC + i * COUT + o0];
            w[2 * v + 1] = (o1 < COUT) ? We[v * CC + i * COUT + o1] : 0.f;
        }
        w[12] = be[i * COUT + o0];
        w[13] = (o1 < COUT) ? be[i * COUT + o1] : 0.f;
        w[14] = 0.f;
        w[15] = 0.f;
    }
    __syncthreads();

    int n = blockIdx.x;
    int start = g_nodeStart[n];
    int end = g_nodeStart[n + 1];

    ull accP[OP];
#pragma unroll
    for (int op = 0; op < OP; op++) accP[op] = 0ull;

    for (int j0 = start; j0 < end; j0 += 128 * TE) {
        ull eaP[TE][6];
        int srcR[TE];
        bool val[TE];
#pragma unroll
        for (int u = 0; u < TE; u++) {
            int j = j0 + u * 128 + threadIdx.x;
            bool v = (j < end);
            int e = g_perm[v ? j : start];
            val[u] = v;
            srcR[u] = src[e];
            const float2* p = (const float2*)(ea + (size_t)e * 6);
            float2 a0 = p[0], a1 = p[1], a2 = p[2];
            eaP[u][0] = f2pk(a0.x, a0.x);
            eaP[u][1] = f2pk(a0.y, a0.y);
            eaP[u][2] = f2pk(a1.x, a1.x);
            eaP[u][3] = f2pk(a1.y, a1.y);
            eaP[u][4] = f2pk(a2.x, a2.x);
            eaP[u][5] = f2pk(a2.y, a2.y);
        }
#pragma unroll 1
        for (int i = 0; i < CIN; i++) {
            ull hsP[TE];
#pragma unroll
            for (int u = 0; u < TE; u++) {
                float h = val[u] ? sH[srcR[u] * CIN + i] : 0.f;
                hsP[u] = f2pk(h, h);
            }
            const ulonglong2* wp = (const ulonglong2*)(sWp + i * (OP * 16));
#pragma unroll
            for (int op = 0; op < OP; op++) {
                ulonglong2 q0 = wp[4 * op + 0];
                ulonglong2 q1 = wp[4 * op + 1];
                ulonglong2 q2 = wp[4 * op + 2];
                ulonglong2 q3 = wp[4 * op + 3];
#pragma unroll
                for (int u = 0; u < TE; u++) {
                    ull t = f2fma(eaP[u][0], q0.x, q3.x);
                    t = f2fma(eaP[u][1], q0.y, t);
                    t = f2fma(eaP[u][2], q1.x, t);
                    t = f2fma(eaP[u][3], q1.y, t);
                    t = f2fma(eaP[u][4], q2.x, t);
                    t = f2fma(eaP[u][5], q2.y, t);
                    float t0, t1;
                    f2un(t, t0, t1);
                    accP[op] = f2fma(hsP[u],
                                     f2pk(fmaxf(t0, 0.f), fmaxf(t1, 0.f)),
                                     accP[op]);
                }
            }
        }
    }

    // reduce: unpack pairs, warp butterfly, cross-warp via smem
    float a0[OP], a1[OP];
#pragma unroll
    for (int op = 0; op < OP; op++) {
        f2un(accP[op], a0[op], a1[op]);
#pragma unroll
        for (int s = 16; s > 0; s >>= 1) {
            a0[op] += __shfl_xor_sync(0xffffffffu, a0[op], s);
            a1[op] += __shfl_xor_sync(0xffffffffu, a1[op], s);
        }
    }
    int wid = threadIdx.x >> 5, lane = threadIdx.x & 31;
    if (lane == 0) {
#pragma unroll
        for (int op = 0; op < OP; op++) {
            wsum[wid * 2 * OP + 2 * op] = a0[op];
            wsum[wid * 2 * OP + 2 * op + 1] = a1[op];
        }
    }
    __syncthreads();
    if (threadIdx.x < COUT) {
        int o = threadIdx.x;
        float s = wsum[o] + wsum[2 * OP + o] + wsum[4 * OP + o] + wsum[6 * OP + o];
        float cnt = (float)(end - start);
        float r = s / fmaxf(cnt, 1.f);
        float d = bias[o];
        for (int i = 0; i < CIN; i++)
            d = fmaf(sH[n * CIN + i], root[i * COUT + o], d);
        hout[n * COUT + o] = fmaxf(r + d, 0.f);
    }
}

// ---------------- pairwise L1 CBT ----------------
__global__ void k_cbt(float* __restrict__ out) {
    __shared__ float sh[NN * 5];
    for (int i = threadIdx.x; i < NN * 5; i += blockDim.x) sh[i] = g_h3[i];
    __syncthreads();
    int gid = blockIdx.x * blockDim.x + threadIdx.x;
    int i = gid >> 9;
    int j = gid & (NN - 1);
    float s = 0.f;
#pragma unroll
    for (int k = 0; k < 5; k++)
        s += fabsf(sh[i * 5 + k] - sh[j * 5 + k]);
    out[gid] = s;
}

// ---------------- launcher ----------------
extern "C" void kernel_launch(void* const* d_in, const int* in_sizes, int n_in,
                              void* d_out, int out_size) {
    const float* x     = (const float*)d_in[0];
    const float* ea    = (const float*)d_in[1];
    const int*   ei    = (const int*)d_in[2];
    const float* We1   = (const float*)d_in[3];
    const float* be1   = (const float*)d_in[4];
    const float* root1 = (const float*)d_in[5];
    const float* b1    = (const float*)d_in[6];
    const float* We2   = (const float*)d_in[7];
    const float* be2   = (const float*)d_in[8];
    const float* root2 = (const float*)d_in[9];
    const float* b2    = (const float*)d_in[10];
    const float* We3   = (const float*)d_in[11];
    const float* be3   = (const float*)d_in[12];
    const float* root3 = (const float*)d_in[13];
    const float* b3    = (const float*)d_in[14];
    float* out = (float*)d_out;

    const int* src = ei;
    const int* dst = ei + NE;

    // smem: NN*CIN + CIN*((COUT+1)/2)*16 floats
    constexpr int SM1 = (NN * 1  + 1  * 18 * 16) * (int)sizeof(float); //  3.2 KB
    constexpr int SM2 = (NN * 36 + 36 * 12 * 16) * (int)sizeof(float); // 101.4 KB
    constexpr int SM3 = (NN * 24 + 24 * 3  * 16) * (int)sizeof(float); // 53.8 KB

    cudaFuncSetAttribute((const void*)k_conv<36, 24, 2>,
                         cudaFuncAttributeMaxDynamicSharedMemorySize, SM2);
    cudaFuncSetAttribute((const void*)k_conv<24, 5, 3>,
                         cudaFuncAttributeMaxDynamicSharedMemorySize, SM3);

    k_hist<<<HB, 256>>>(dst);
    k_scan<<<1, NN>>>();
    k_scatter<<<HB, 256>>>(dst);

    k_conv<1, 36, 1><<<NN, 128, SM1>>>(x, ea, src, We1, be1, root1, b1);
    k_conv<36, 24, 2><<<NN, 128, SM2>>>(x, ea, src, We2, be2, root2, b2);
    k_conv<24, 5, 3><<<NN, 128, SM3>>>(x, ea, src, We3, be3, root3, b3);

    k_cbt<<<NE / 256, 256>>>(out);
}